// round 8
// baseline (speedup 1.0000x reference)
#include <cuda_runtime.h>
#include <cuda_bf16.h>
#include <cstdint>

// RBF_Conv2d: x (16,1,256,256) f32, w (64,1,5,5) f32 -> out (16,64,252,252) f32
// out[b,o,h,w] = exp(-0.5 * d^2 / var_hw),  d = sqrt(max(||patch-w||^2,1e-12))
// var_hw = sample var (ddof=1) of d over the (B*O)=1024 matrix at pixel (h,w)

#define B_  16
#define O_  64
#define HO  252
#define WO  252
#define WT  12      // w-pixels per block
#define HB  2       // h-rows per block

typedef unsigned long long u64;

__device__ __forceinline__ u64 fma2(u64 a, u64 b, u64 c) {
    u64 d; asm("fma.rn.f32x2 %0, %1, %2, %3;" : "=l"(d) : "l"(a), "l"(b), "l"(c)); return d;
}
__device__ __forceinline__ u64 add2(u64 a, u64 b) {
    u64 d; asm("add.rn.f32x2 %0, %1, %2;" : "=l"(d) : "l"(a), "l"(b)); return d;
}
__device__ __forceinline__ u64 sub2(u64 a, u64 b) {
    u64 d; asm("sub.rn.f32x2 %0, %1, %2;" : "=l"(d) : "l"(a), "l"(b)); return d;
}
__device__ __forceinline__ u64 pack2(float lo, float hi) {
    u64 d; asm("mov.b64 %0, {%1, %2};" : "=l"(d) : "f"(lo), "f"(hi)); return d;
}
__device__ __forceinline__ void unpack2(u64 v, float& lo, float& hi) {
    asm("mov.b64 {%0, %1}, %2;" : "=f"(lo), "=f"(hi) : "l"(v));
}
// odd-aligned pair {hi(a), lo(b)} built in registers (ALU pipe)
__device__ __forceinline__ u64 mkodd(u64 a, u64 b) {
    u64 r;
    asm("{\n\t"
        ".reg .b32 alo, ahi, blo, bhi;\n\t"
        "mov.b64 {alo, ahi}, %1;\n\t"
        "mov.b64 {blo, bhi}, %2;\n\t"
        "mov.b64 %0, {ahi, blo};\n\t"
        "}" : "=l"(r) : "l"(a), "l"(b));
    return r;
}
__device__ __forceinline__ float ex2_approx(float a) {
    float r; asm("ex2.approx.ftz.f32 %0, %1;" : "=f"(r) : "f"(a)); return r;
}
__device__ __forceinline__ float sqrt_approx(float a) {
    float r; asm("sqrt.approx.ftz.f32 %0, %1;" : "=f"(r) : "f"(a)); return r;
}

__global__ __launch_bounds__(512, 2)
void rbf_conv2d_kernel(const float* __restrict__ x,
                       const float* __restrict__ w,
                       float* __restrict__ out)
{
    __shared__ __align__(16) float xs [B_][6][16];   // rows h0..h0+5, cols w0..w0+15
    __shared__ __align__(16) float ws [25][O_];      // weights transposed [k][o]
    __shared__ __align__(16) float wns[O_];          // wn[o] = sum_k w^2
    __shared__ __align__(16) float pns[HB][B_][WT];  // patch norms per h-row
    __shared__ __align__(16) float red[WT][16];      // [w][warp] partials
    __shared__ __align__(16) float mean_s[WT];
    __shared__ __align__(16) float cinv_s[WT];

    const int tid  = threadIdx.x;
    const int h0   = blockIdx.y * HB;
    const int w0   = blockIdx.x * WT;
    const int lane = tid & 31;
    const int warp = tid >> 5;           // == batch index b (warp-uniform)
    const int og   = lane & 15;          // o-group: 4 o's per lane
    const int wh   = lane >> 4;          // w-half: 0 -> w 0..5, 1 -> w 6..11
    const int o0   = og * 4;

    // ---- stage weights transposed ----
    for (int i = tid; i < 25 * O_; i += 512) {
        int k = i >> 6, o = i & 63;
        ws[k][o] = w[o * 25 + k];
    }
    // ---- stage x window: 16 b x 6 rows x 16 cols (all in-bounds) ----
    for (int i = tid; i < B_ * 6 * 16; i += 512) {
        int b = i / 96;
        int r = (i >> 4) % 6;
        int c = i & 15;
        xs[b][r][c] = x[b * 65536 + (h0 + r) * 256 + (w0 + c)];
    }
    __syncthreads();

    // ---- weight norms (64 threads) + patch norms (384 threads) ----
    if (tid < O_) {
        float s = 0.f;
        #pragma unroll
        for (int k = 0; k < 25; k++) {
            float v = ws[k][tid];
            s = fmaf(v, v, s);
        }
        wns[tid] = s;
    } else if (tid >= 128) {
        int t  = tid - 128;              // 0..383
        int hr = t / 192;
        int rr = t % 192;
        int b  = rr / WT, wi = rr % WT;
        float s = 0.f;
        #pragma unroll
        for (int kh = 0; kh < 5; kh++)
            #pragma unroll
            for (int kw = 0; kw < 5; kw++) {
                float v = xs[b][hr + kh][wi + kw];
                s = fmaf(v, v, s);
            }
        pns[hr][b][wi] = s;
    }
    __syncthreads();

    const float4 wnv = *(const float4*)&wns[o0];
    u64 wnp[4];
    wnp[0] = pack2(wnv.x, wnv.x); wnp[1] = pack2(wnv.y, wnv.y);
    wnp[2] = pack2(wnv.z, wnv.z); wnp[3] = pack2(wnv.w, wnv.w);
    const u64 m2 = pack2(-2.f, -2.f);

    #pragma unroll
    for (int hr = 0; hr < HB; hr++) {
        const int h = h0 + hr;

        // ---- mainloop: tile 1b x 4o x 6w (3 packed w-pairs) ----
        u64 acc[4][3];
        #pragma unroll
        for (int o = 0; o < 4; o++)
            #pragma unroll
            for (int q = 0; q < 3; q++) acc[o][q] = 0ull;

        #pragma unroll
        for (int kh = 0; kh < 5; kh++) {
            const float* rowp = &xs[warp][hr + kh][6 * wh];
            u64 ev[5];
            #pragma unroll
            for (int p = 0; p < 5; p++) ev[p] = *(const u64*)(rowp + 2 * p);
            u64 od[4];
            #pragma unroll
            for (int i = 0; i < 4; i++) od[i] = mkodd(ev[i], ev[i + 1]);

            #pragma unroll
            for (int kw = 0; kw < 5; kw++) {
                float4 wv = *(const float4*)&ws[kh * 5 + kw][o0];
                u64 wp[4];
                wp[0] = pack2(wv.x, wv.x); wp[1] = pack2(wv.y, wv.y);
                wp[2] = pack2(wv.z, wv.z); wp[3] = pack2(wv.w, wv.w);
                #pragma unroll
                for (int q = 0; q < 3; q++) {
                    u64 m = ((kw & 1) == 0) ? ev[q + (kw >> 1)] : od[q + ((kw - 1) >> 1)];
                    #pragma unroll
                    for (int o = 0; o < 4; o++)
                        acc[o][q] = fma2(m, wp[o], acc[o][q]);
                }
            }
        }

        // ---- d = sqrt(max(pn + wn - 2*cross, 1e-12)); pass-1 local sums ----
        const u64* pnp = (const u64*)&pns[hr][warp][6 * wh];
        u64 pnq[3];
        #pragma unroll
        for (int q = 0; q < 3; q++) pnq[q] = pnp[q];

        u64 distp[4][3];
        float sums[6];
        #pragma unroll
        for (int j = 0; j < 6; j++) sums[j] = 0.f;

        #pragma unroll
        for (int o = 0; o < 4; o++)
            #pragma unroll
            for (int q = 0; q < 3; q++) {
                u64 d2p = fma2(acc[o][q], m2, add2(pnq[q], wnp[o]));
                float a, bb;
                unpack2(d2p, a, bb);
                a  = fmaxf(a,  1e-12f);
                bb = fmaxf(bb, 1e-12f);
                float da = sqrt_approx(a);
                float db = sqrt_approx(bb);
                distp[o][q] = pack2(da, db);
                sums[2 * q]     += da;
                sums[2 * q + 1] += db;
            }

        // ---- pass 1: o-reduction over 16 lanes (4 levels x 6 vals = 24 shfl) ----
        #pragma unroll
        for (int off = 8; off; off >>= 1)
            #pragma unroll
            for (int j = 0; j < 6; j++)
                sums[j] += __shfl_xor_sync(0xffffffffu, sums[j], off);
        if (og == 0) {
            #pragma unroll
            for (int j = 0; j < 6; j++) red[6 * wh + j][warp] = sums[j];
        }
        __syncthreads();
        if (tid < WT) {
            const float4* rp = (const float4*)&red[tid][0];
            float4 r0 = rp[0], r1 = rp[1], r2 = rp[2], r3 = rp[3];
            float s = ((r0.x + r0.y) + (r0.z + r0.w)) + ((r1.x + r1.y) + (r1.z + r1.w))
                    + ((r2.x + r2.y) + (r2.z + r2.w)) + ((r3.x + r3.y) + (r3.z + r3.w));
            mean_s[tid] = s * (1.0f / 1024.0f);
        }
        __syncthreads();

        // ---- pass 2: sum (d - mean)^2, packed ----
        u64 ml[3];
        #pragma unroll
        for (int q = 0; q < 3; q++) ml[q] = *(const u64*)&mean_s[6 * wh + 2 * q];
        u64 sp[3];
        #pragma unroll
        for (int q = 0; q < 3; q++) sp[q] = 0ull;
        #pragma unroll
        for (int o = 0; o < 4; o++)
            #pragma unroll
            for (int q = 0; q < 3; q++) {
                u64 dd = sub2(distp[o][q], ml[q]);
                sp[q] = fma2(dd, dd, sp[q]);
            }
        float s2[6];
        #pragma unroll
        for (int q = 0; q < 3; q++) unpack2(sp[q], s2[2 * q], s2[2 * q + 1]);
        #pragma unroll
        for (int off = 8; off; off >>= 1)
            #pragma unroll
            for (int j = 0; j < 6; j++)
                s2[j] += __shfl_xor_sync(0xffffffffu, s2[j], off);
        if (og == 0) {
            #pragma unroll
            for (int j = 0; j < 6; j++) red[6 * wh + j][warp] = s2[j];
        }
        __syncthreads();
        if (tid < WT) {
            const float4* rp = (const float4*)&red[tid][0];
            float4 r0 = rp[0], r1 = rp[1], r2 = rp[2], r3 = rp[3];
            float s = ((r0.x + r0.y) + (r0.z + r0.w)) + ((r1.x + r1.y) + (r1.z + r1.w))
                    + ((r2.x + r2.y) + (r2.z + r2.w)) + ((r3.x + r3.y) + (r3.z + r3.w));
            float var = s * (1.0f / 1023.0f);
            // exp(-0.5*d^2/var) = exp2( d^2 * (-0.5*log2(e)/var) )
            cinv_s[tid] = -0.72134752044448170368f / var;
        }
        __syncthreads();

        // ---- output: per (b,o) 6 contiguous floats (float2 x3) ----
        float cl[6];
        #pragma unroll
        for (int q = 0; q < 3; q++) {
            u64 c2 = *(const u64*)&cinv_s[6 * wh + 2 * q];
            unpack2(c2, cl[2 * q], cl[2 * q + 1]);
        }
        #pragma unroll
        for (int o = 0; o < 4; o++) {
            size_t base = ((size_t)(warp * O_ + (o0 + o)) * HO + h) * WO + w0 + 6 * wh;
            #pragma unroll
            for (int q = 0; q < 3; q++) {
                float d0, d1;
                unpack2(distp[o][q], d0, d1);
                float2 v;
                v.x = ex2_approx(cl[2 * q]     * d0 * d0);
                v.y = ex2_approx(cl[2 * q + 1] * d1 * d1);
                *(float2*)&out[base + 2 * q] = v;
            }
        }
    }
}

extern "C" void kernel_launch(void* const* d_in, const int* in_sizes, int n_in,
                              void* d_out, int out_size)
{
    const float* x = (const float*)d_in[0];      // (16,1,256,256)
    const float* w = (const float*)d_in[1];      // (64,1,5,5)
    float* out = (float*)d_out;                  // (16,64,252,252)

    dim3 grid(WO / WT, HO / HB);                 // (21, 126)
    rbf_conv2d_kernel<<<grid, 512>>>(x, w, out);
}

// round 9
// speedup vs baseline: 1.0465x; 1.0465x over previous
#include <cuda_runtime.h>
#include <cuda_bf16.h>
#include <cstdint>

// RBF_Conv2d: x (16,1,256,256) f32, w (64,1,5,5) f32 -> out (16,64,252,252) f32
// out[b,o,h,w] = exp(-0.5 * d^2 / var_hw),  d = sqrt(max(||patch-w||^2,1e-12))
// var_hw = sample var (ddof=1) of d over the (B*O)=1024 matrix at pixel (h,w)
// Variance via two-level (Chan) merge: per-warp (mean, S2), merged once.

#define B_  16
#define O_  64
#define HO  252
#define WO  252
#define WT  12      // w-pixels per block (252 = 21*12)
#define WIN 16      // window cols staged (WT + 4, padded to 16)
#define NQ  6       // WT/2 packed pairs

typedef unsigned long long u64;

__device__ __forceinline__ u64 fma2(u64 a, u64 b, u64 c) {
    u64 d; asm("fma.rn.f32x2 %0, %1, %2, %3;" : "=l"(d) : "l"(a), "l"(b), "l"(c)); return d;
}
__device__ __forceinline__ u64 add2(u64 a, u64 b) {
    u64 d; asm("add.rn.f32x2 %0, %1, %2;" : "=l"(d) : "l"(a), "l"(b)); return d;
}
__device__ __forceinline__ u64 pack2(float lo, float hi) {
    u64 d; asm("mov.b64 %0, {%1, %2};" : "=l"(d) : "f"(lo), "f"(hi)); return d;
}
__device__ __forceinline__ void unpack2(u64 v, float& lo, float& hi) {
    asm("mov.b64 {%0, %1}, %2;" : "=f"(lo), "=f"(hi) : "l"(v));
}
// odd-aligned pair {hi(a), lo(b)} built in registers (ALU pipe, no LDS)
__device__ __forceinline__ u64 mkodd(u64 a, u64 b) {
    u64 r;
    asm("{\n\t"
        ".reg .b32 alo, ahi, blo, bhi;\n\t"
        "mov.b64 {alo, ahi}, %1;\n\t"
        "mov.b64 {blo, bhi}, %2;\n\t"
        "mov.b64 %0, {ahi, blo};\n\t"
        "}" : "=l"(r) : "l"(a), "l"(b));
    return r;
}
__device__ __forceinline__ float ex2_approx(float a) {
    float r; asm("ex2.approx.ftz.f32 %0, %1;" : "=f"(r) : "f"(a)); return r;
}
__device__ __forceinline__ float sqrt_approx(float a) {
    float r; asm("sqrt.approx.ftz.f32 %0, %1;" : "=f"(r) : "f"(a)); return r;
}

__global__ __launch_bounds__(512, 2)
void rbf_conv2d_kernel(const float* __restrict__ x,
                       const float* __restrict__ w,
                       float* __restrict__ out)
{
    __shared__ __align__(16) float xs [B_][5][WIN];  // window cols w0..w0+15
    __shared__ __align__(16) float ws [25][O_];      // weights transposed [k][o]
    __shared__ __align__(16) float wns[O_];          // wn[o] = sum_k w[o][k]^2
    __shared__ __align__(16) float pns[B_][WT];      // patch norms
    __shared__ __align__(16) float redC[WT][16];     // [w][warp] warp sums of d
    __shared__ __align__(16) float redS[WT][16];     // [w][warp] warp S2
    __shared__ __align__(16) float cinv_s[WT];

    const int tid  = threadIdx.x;
    const int h    = blockIdx.y;
    const int w0   = blockIdx.x * WT;
    const int lane = tid & 31;
    const int warp = tid >> 5;           // == batch index b (warp-uniform)

    // ---- weights transposed ----
    for (int i = tid; i < 25 * O_; i += 512) {
        int k = i >> 6, o = i & 63;
        ws[k][o] = w[o * 25 + k];
    }
    // ---- x window ----
    for (int i = tid; i < B_ * 5 * WIN; i += 512) {
        int b = i / (5 * WIN);
        int r = (i / WIN) % 5;
        int c = i & (WIN - 1);
        xs[b][r][c] = x[b * 65536 + (h + r) * 256 + (w0 + c)];  // w0+c <= 255
    }
    __syncthreads();

    // ---- weight norms (64 threads) + patch norms (192 threads) ----
    if (tid < O_) {
        float s = 0.f;
        #pragma unroll
        for (int k = 0; k < 25; k++) {
            float v = ws[k][tid];
            s = fmaf(v, v, s);
        }
        wns[tid] = s;
    } else if (tid >= 64 && tid < 64 + B_ * WT) {
        int t = tid - 64;
        int b = t / WT, wi = t % WT;
        float s = 0.f;
        #pragma unroll
        for (int kh = 0; kh < 5; kh++)
            #pragma unroll
            for (int kw = 0; kw < 5; kw++) {
                float v = xs[b][kh][wi + kw];
                s = fmaf(v, v, s);
            }
        pns[b][wi] = s;
    }
    __syncthreads();

    // ---- thread tile: 1 b x 2 o x 12 w (6 packed pairs) ----
    const int b  = warp;                 // warp-uniform -> broadcast LDS
    const int o0 = lane * 2;

    u64 acc0[NQ], acc1[NQ];
    #pragma unroll
    for (int q = 0; q < NQ; q++) { acc0[q] = 0ull; acc1[q] = 0ull; }

    #pragma unroll
    for (int kh = 0; kh < 5; kh++) {
        // 8 even pairs via 4x LDS.128 (warp-broadcast)
        u64 ev[8];
        {
            const uint4* p = (const uint4*)&xs[b][kh][0];
            #pragma unroll
            for (int t = 0; t < 4; t++) {
                uint4 v = p[t];
                ev[2 * t]     = (u64)v.x | ((u64)v.y << 32);
                ev[2 * t + 1] = (u64)v.z | ((u64)v.w << 32);
            }
        }
        // 7 odd pairs in registers (ALU)
        u64 od[7];
        #pragma unroll
        for (int i = 0; i < 7; i++) od[i] = mkodd(ev[i], ev[i + 1]);

        #pragma unroll
        for (int kw = 0; kw < 5; kw++) {
            float2 wv = *(const float2*)&ws[kh * 5 + kw][o0];
            u64 wp0 = pack2(wv.x, wv.x);
            u64 wp1 = pack2(wv.y, wv.y);
            #pragma unroll
            for (int q = 0; q < NQ; q++) {
                u64 m = ((kw & 1) == 0) ? ev[q + (kw >> 1)] : od[q + ((kw - 1) >> 1)];
                acc0[q] = fma2(m, wp0, acc0[q]);
                acc1[q] = fma2(m, wp1, acc1[q]);
            }
        }
    }

    // ---- d = sqrt(max(pn + wn - 2*cross, 1e-12)); local per-w sums ----
    float2 wnv = *(const float2*)&wns[o0];
    float dist[2][WT];
    float sums[WT];
    #pragma unroll
    for (int wi = 0; wi < WT; wi++) sums[wi] = 0.f;

    const u64 m2 = pack2(-2.f, -2.f);
    const u64* pnp = (const u64*)&pns[b][0];
    #pragma unroll
    for (int j = 0; j < 2; j++) {
        const float wn = j ? wnv.y : wnv.x;
        const u64 wnp = pack2(wn, wn);
        #pragma unroll
        for (int q = 0; q < NQ; q++) {
            u64 d2p = fma2(j ? acc1[q] : acc0[q], m2, add2(pnp[q], wnp));
            float a, bb;
            unpack2(d2p, a, bb);
            a  = fmaxf(a,  1e-12f);
            bb = fmaxf(bb, 1e-12f);
            float da = sqrt_approx(a);
            float db = sqrt_approx(bb);
            dist[j][2 * q]     = da;
            dist[j][2 * q + 1] = db;
            sums[2 * q]     += da;
            sums[2 * q + 1] += db;
        }
    }

    // ---- warp-local sum of d over 64 o's (butterfly, all lanes get result) ----
    #pragma unroll
    for (int off = 16; off; off >>= 1)
        #pragma unroll
        for (int wi = 0; wi < WT; wi++)
            sums[wi] += __shfl_xor_sync(0xffffffffu, sums[wi], off);
    if (lane == 0) {
        #pragma unroll
        for (int wi = 0; wi < WT; wi++) redC[wi][warp] = sums[wi];
    }

    // ---- warp-local S2 = sum (d - c_w)^2, c_w = sums/64 (no barrier needed) ----
    float s2[WT];
    #pragma unroll
    for (int wi = 0; wi < WT; wi++) s2[wi] = 0.f;
    #pragma unroll
    for (int j = 0; j < 2; j++)
        #pragma unroll
        for (int wi = 0; wi < WT; wi++) {
            float dd = fmaf(sums[wi], -1.0f / 64.0f, dist[j][wi]);  // d - c_w
            s2[wi] = fmaf(dd, dd, s2[wi]);
        }
    #pragma unroll
    for (int off = 16; off; off >>= 1)
        #pragma unroll
        for (int wi = 0; wi < WT; wi++)
            s2[wi] += __shfl_xor_sync(0xffffffffu, s2[wi], off);
    if (lane == 0) {
        #pragma unroll
        for (int wi = 0; wi < WT; wi++) redS[wi][warp] = s2[wi];
    }
    __syncthreads();

    // ---- finalize (12 threads): Chan merge of 16 warp stats ----
    if (tid < WT) {
        const float4* cp = (const float4*)&redC[tid][0];
        float4 c0 = cp[0], c1 = cp[1], c2 = cp[2], c3 = cp[3];
        const float4* sp = (const float4*)&redS[tid][0];
        float4 s0 = sp[0], s1 = sp[1], s2v = sp[2], s3 = sp[3];
        float csum = ((c0.x + c0.y) + (c0.z + c0.w)) + ((c1.x + c1.y) + (c1.z + c1.w))
                   + ((c2.x + c2.y) + (c2.z + c2.w)) + ((c3.x + c3.y) + (c3.z + c3.w));
        float S2w  = ((s0.x + s0.y) + (s0.z + s0.w)) + ((s1.x + s1.y) + (s1.z + s1.w))
                   + ((s2v.x + s2v.y) + (s2v.z + s2v.w)) + ((s3.x + s3.y) + (s3.z + s3.w));
        float mean = csum * (1.0f / 1024.0f);
        // between-warp term: 64 * sum_w (c_w - mean)^2, c_w = csum_w/64
        float bsum = 0.f;
        float cw[16] = {c0.x, c0.y, c0.z, c0.w, c1.x, c1.y, c1.z, c1.w,
                        c2.x, c2.y, c2.z, c2.w, c3.x, c3.y, c3.z, c3.w};
        #pragma unroll
        for (int r = 0; r < 16; r++) {
            float dd = fmaf(cw[r], 1.0f / 64.0f, -mean);
            bsum = fmaf(dd, dd, bsum);
        }
        float S2tot = S2w + 64.0f * bsum;
        float var = S2tot * (1.0f / 1023.0f);
        // exp(-0.5*d^2/var) = exp2( d^2 * (-0.5*log2(e)/var) )
        cinv_s[tid] = -0.72134752044448170368f / var;
    }
    __syncthreads();

    float cl[WT];
    #pragma unroll
    for (int wi = 0; wi < WT; wi++) cl[wi] = cinv_s[wi];

    // ---- write out: per (b,o) 12 contiguous floats (float4 x3) ----
    #pragma unroll
    for (int j = 0; j < 2; j++) {
        size_t base = ((size_t)(b * O_ + (o0 + j)) * HO + h) * WO + w0;
        #pragma unroll
        for (int g = 0; g < WT; g += 4) {
            float d0 = dist[j][g + 0];
            float d1 = dist[j][g + 1];
            float d2v = dist[j][g + 2];
            float d3 = dist[j][g + 3];
            float4 v;
            v.x = ex2_approx(cl[g + 0] * d0 * d0);
            v.y = ex2_approx(cl[g + 1] * d1 * d1);
            v.z = ex2_approx(cl[g + 2] * d2v * d2v);
            v.w = ex2_approx(cl[g + 3] * d3 * d3);
            *(float4*)&out[base + g] = v;
        }
    }
}

extern "C" void kernel_launch(void* const* d_in, const int* in_sizes, int n_in,
                              void* d_out, int out_size)
{
    const float* x = (const float*)d_in[0];      // (16,1,256,256)
    const float* w = (const float*)d_in[1];      // (64,1,5,5)
    float* out = (float*)d_out;                  // (16,64,252,252)

    dim3 grid(WO / WT, HO);                      // (21, 252)
    rbf_conv2d_kernel<<<grid, 512>>>(x, w, out);
}

// round 10
// speedup vs baseline: 1.1221x; 1.0723x over previous
#include <cuda_runtime.h>
#include <cuda_bf16.h>
#include <cstdint>

// RBF_Conv2d: x (16,1,256,256) f32, w (64,1,5,5) f32 -> out (16,64,252,252) f32
// out[b,o,h,w] = exp(-0.5 * d^2 / var_hw),  d = sqrt(max(||patch-w||^2,1e-12))
// var_hw = sample var (ddof=1) of d over the (B*O)=1024 matrix at pixel (h,w)
// Warp reductions via fixed-point redux.sync.add.u32; Chan two-level variance merge.

#define B_  16
#define O_  64
#define HO  252
#define WO  252
#define WT  12      // w-pixels per block (252 = 21*12)
#define WIN 16      // window cols staged (WT + 4, padded to 16)
#define NQ  6       // WT/2 packed pairs

#define SCALE2  1.099511627776e12f   // 2^40  (applied to d^2)
#define INV_S2  9.094947017729282e-13f // 2^-40
#define S2_RES  5.9604644775390625e-8f // 2^-24 (pass-2 rescale -> 2^16 fixed point)
#define S2_BACK 1.52587890625e-5f      // 2^-16

typedef unsigned long long u64;

__device__ __forceinline__ u64 fma2(u64 a, u64 b, u64 c) {
    u64 d; asm("fma.rn.f32x2 %0, %1, %2, %3;" : "=l"(d) : "l"(a), "l"(b), "l"(c)); return d;
}
__device__ __forceinline__ u64 add2(u64 a, u64 b) {
    u64 d; asm("add.rn.f32x2 %0, %1, %2;" : "=l"(d) : "l"(a), "l"(b)); return d;
}
__device__ __forceinline__ u64 pack2(float lo, float hi) {
    u64 d; asm("mov.b64 %0, {%1, %2};" : "=l"(d) : "f"(lo), "f"(hi)); return d;
}
__device__ __forceinline__ void unpack2(u64 v, float& lo, float& hi) {
    asm("mov.b64 {%0, %1}, %2;" : "=f"(lo), "=f"(hi) : "l"(v));
}
// odd-aligned pair {hi(a), lo(b)} built in registers (ALU pipe, no LDS)
__device__ __forceinline__ u64 mkodd(u64 a, u64 b) {
    u64 r;
    asm("{\n\t"
        ".reg .b32 alo, ahi, blo, bhi;\n\t"
        "mov.b64 {alo, ahi}, %1;\n\t"
        "mov.b64 {blo, bhi}, %2;\n\t"
        "mov.b64 %0, {ahi, blo};\n\t"
        "}" : "=l"(r) : "l"(a), "l"(b));
    return r;
}
__device__ __forceinline__ unsigned redux_u32(unsigned v) {
    unsigned r; asm("redux.sync.add.u32 %0, %1, 0xffffffff;" : "=r"(r) : "r"(v)); return r;
}
__device__ __forceinline__ float ex2_approx(float a) {
    float r; asm("ex2.approx.ftz.f32 %0, %1;" : "=f"(r) : "f"(a)); return r;
}
__device__ __forceinline__ float sqrt_approx(float a) {
    float r; asm("sqrt.approx.ftz.f32 %0, %1;" : "=f"(r) : "f"(a)); return r;
}

__global__ __launch_bounds__(512, 2)
void rbf_conv2d_kernel(const float* __restrict__ x,
                       const float* __restrict__ w,
                       float* __restrict__ out)
{
    __shared__ __align__(16) float xs [B_][5][WIN];  // window cols w0..w0+15
    __shared__ __align__(16) float ws [25][O_];      // weights transposed [k][o]
    __shared__ __align__(16) float wns[O_];          // wn[o]*2^40
    __shared__ __align__(16) float pns[B_][WT];      // patch norms *2^40
    __shared__ __align__(16) float redC[WT][16];     // [w][warp] warp sums of d (2^20)
    __shared__ __align__(16) float redS[WT][16];     // [w][warp] warp S2 (2^16)
    __shared__ __align__(16) float cinv_s[WT];

    const int tid  = threadIdx.x;
    const int h    = blockIdx.y;
    const int w0   = blockIdx.x * WT;
    const int lane = tid & 31;
    const int warp = tid >> 5;           // == batch index b (warp-uniform)

    // ---- weights transposed ----
    for (int i = tid; i < 25 * O_; i += 512) {
        int k = i >> 6, o = i & 63;
        ws[k][o] = w[o * 25 + k];
    }
    // ---- x window ----
    for (int i = tid; i < B_ * 5 * WIN; i += 512) {
        int b = i / (5 * WIN);
        int r = (i / WIN) % 5;
        int c = i & (WIN - 1);
        xs[b][r][c] = x[b * 65536 + (h + r) * 256 + (w0 + c)];  // w0+c <= 255
    }
    __syncthreads();

    // ---- weight norms (scaled 2^40) + patch norms (scaled 2^40) ----
    if (tid < O_) {
        float s = 0.f;
        #pragma unroll
        for (int k = 0; k < 25; k++) {
            float v = ws[k][tid];
            s = fmaf(v, v, s);
        }
        wns[tid] = s * SCALE2;
    } else if (tid >= 64 && tid < 64 + B_ * WT) {
        int t = tid - 64;
        int b = t / WT, wi = t % WT;
        float s = 0.f;
        #pragma unroll
        for (int kh = 0; kh < 5; kh++)
            #pragma unroll
            for (int kw = 0; kw < 5; kw++) {
                float v = xs[b][kh][wi + kw];
                s = fmaf(v, v, s);
            }
        pns[b][wi] = s * SCALE2;
    }
    __syncthreads();

    // ---- thread tile: 1 b x 2 o x 12 w (6 packed pairs) ----
    const int b  = warp;                 // warp-uniform -> broadcast LDS
    const int o0 = lane * 2;

    u64 acc0[NQ], acc1[NQ];
    #pragma unroll
    for (int q = 0; q < NQ; q++) { acc0[q] = 0ull; acc1[q] = 0ull; }

    #pragma unroll
    for (int kh = 0; kh < 5; kh++) {
        // 8 even pairs via 4x LDS.128 (warp-broadcast)
        u64 ev[8];
        {
            const uint4* p = (const uint4*)&xs[b][kh][0];
            #pragma unroll
            for (int t = 0; t < 4; t++) {
                uint4 v = p[t];
                ev[2 * t]     = (u64)v.x | ((u64)v.y << 32);
                ev[2 * t + 1] = (u64)v.z | ((u64)v.w << 32);
            }
        }
        // 7 odd pairs in registers (ALU)
        u64 od[7];
        #pragma unroll
        for (int i = 0; i < 7; i++) od[i] = mkodd(ev[i], ev[i + 1]);

        #pragma unroll
        for (int kw = 0; kw < 5; kw++) {
            float2 wv = *(const float2*)&ws[kh * 5 + kw][o0];
            u64 wp0 = pack2(wv.x, wv.x);
            u64 wp1 = pack2(wv.y, wv.y);
            #pragma unroll
            for (int q = 0; q < NQ; q++) {
                u64 m = ((kw & 1) == 0) ? ev[q + (kw >> 1)] : od[q + ((kw - 1) >> 1)];
                acc0[q] = fma2(m, wp0, acc0[q]);
                acc1[q] = fma2(m, wp1, acc1[q]);
            }
        }
    }

    // ---- d_s = sqrt(max(d2*2^40, 1.1)) = d*2^20; local per-w sums ----
    float2 wnv = *(const float2*)&wns[o0];
    float dist[2][WT];                   // scaled by 2^20
    float sums[WT];
    #pragma unroll
    for (int wi = 0; wi < WT; wi++) sums[wi] = 0.f;

    const u64 m2 = pack2(-2.f * SCALE2, -2.f * SCALE2);
    const u64* pnp = (const u64*)&pns[b][0];
    #pragma unroll
    for (int j = 0; j < 2; j++) {
        const float wn = j ? wnv.y : wnv.x;
        const u64 wnp = pack2(wn, wn);
        #pragma unroll
        for (int q = 0; q < NQ; q++) {
            u64 d2p = fma2(j ? acc1[q] : acc0[q], m2, add2(pnp[q], wnp));
            float a, bb;
            unpack2(d2p, a, bb);
            a  = fmaxf(a,  1.0995f);     // 1e-12 * 2^40
            bb = fmaxf(bb, 1.0995f);
            float da = sqrt_approx(a);
            float db = sqrt_approx(bb);
            dist[j][2 * q]     = da;
            dist[j][2 * q + 1] = db;
            sums[2 * q]     += da;
            sums[2 * q + 1] += db;
        }
    }

    // ---- warp sum of d over 64 o's via u32 redux (result in all lanes) ----
    float csumf[WT];
    #pragma unroll
    for (int wi = 0; wi < WT; wi++) {
        unsigned su = __float2uint_rn(sums[wi]);
        csumf[wi] = __uint2float_rn(redux_u32(su));   // Σ64 d, scaled 2^20
    }
    if (lane == 0) {
        #pragma unroll
        for (int wi = 0; wi < WT; wi++) redC[wi][warp] = csumf[wi];
    }

    // ---- warp-local S2 = Σ(d - c_w)^2 (scaled 2^40 -> 2^16 fixed point) ----
    #pragma unroll
    for (int wi = 0; wi < WT; wi++) {
        float dd0 = fmaf(csumf[wi], -1.0f / 64.0f, dist[0][wi]);
        float dd1 = fmaf(csumf[wi], -1.0f / 64.0f, dist[1][wi]);
        float s2 = fmaf(dd1, dd1, dd0 * dd0);         // scaled 2^40
        unsigned su = __float2uint_rn(s2 * S2_RES);   // scaled 2^16
        unsigned r = redux_u32(su);
        if (lane == 0) redS[wi][warp] = __uint2float_rn(r);
    }
    __syncthreads();

    // ---- finalize (12 threads): Chan merge of 16 warp stats ----
    if (tid < WT) {
        const float4* cp = (const float4*)&redC[tid][0];
        float4 c0 = cp[0], c1 = cp[1], c2 = cp[2], c3 = cp[3];
        const float4* sp = (const float4*)&redS[tid][0];
        float4 s0 = sp[0], s1 = sp[1], s2v = sp[2], s3 = sp[3];
        float csum = ((c0.x + c0.y) + (c0.z + c0.w)) + ((c1.x + c1.y) + (c1.z + c1.w))
                   + ((c2.x + c2.y) + (c2.z + c2.w)) + ((c3.x + c3.y) + (c3.z + c3.w));
        float S2w  = ((s0.x + s0.y) + (s0.z + s0.w)) + ((s1.x + s1.y) + (s1.z + s1.w))
                   + ((s2v.x + s2v.y) + (s2v.z + s2v.w)) + ((s3.x + s3.y) + (s3.z + s3.w));
        float mean = csum * (1.0f / 1024.0f);         // scaled 2^20
        float bsum = 0.f;                             // scaled 2^40
        float cw[16] = {c0.x, c0.y, c0.z, c0.w, c1.x, c1.y, c1.z, c1.w,
                        c2.x, c2.y, c2.z, c2.w, c3.x, c3.y, c3.z, c3.w};
        #pragma unroll
        for (int r = 0; r < 16; r++) {
            float dd = fmaf(cw[r], 1.0f / 64.0f, -mean);
            bsum = fmaf(dd, dd, bsum);
        }
        // real S2 = S2w*2^-16 + 64*bsum*2^-40
        float S2tot = fmaf(S2w, S2_BACK, 64.0f * bsum * INV_S2);
        float var = S2tot * (1.0f / 1023.0f);
        // out = exp2( d^2 * (-0.5*log2(e)/var) ); d_s^2 = d^2 * 2^40
        cinv_s[tid] = (-0.72134752044448170368f * INV_S2) / var;
    }
    __syncthreads();

    float cl[WT];
    #pragma unroll
    for (int wi = 0; wi < WT; wi++) cl[wi] = cinv_s[wi];

    // ---- write out: per (b,o) 12 contiguous floats (float4 x3) ----
    #pragma unroll
    for (int j = 0; j < 2; j++) {
        size_t base = ((size_t)(b * O_ + (o0 + j)) * HO + h) * WO + w0;
        #pragma unroll
        for (int g = 0; g < WT; g += 4) {
            float d0 = dist[j][g + 0];
            float d1 = dist[j][g + 1];
            float d2v = dist[j][g + 2];
            float d3 = dist[j][g + 3];
            float4 v;
            v.x = ex2_approx(cl[g + 0] * d0 * d0);
            v.y = ex2_approx(cl[g + 1] * d1 * d1);
            v.z = ex2_approx(cl[g + 2] * d2v * d2v);
            v.w = ex2_approx(cl[g + 3] * d3 * d3);
            *(float4*)&out[base + g] = v;
        }
    }
}

extern "C" void kernel_launch(void* const* d_in, const int* in_sizes, int n_in,
                              void* d_out, int out_size)
{
    const float* x = (const float*)d_in[0];      // (16,1,256,256)
    const float* w = (const float*)d_in[1];      // (64,1,5,5)
    float* out = (float*)d_out;                  // (16,64,252,252)

    dim3 grid(WO / WT, HO);                      // (21, 252)
    rbf_conv2d_kernel<<<grid, 512>>>(x, w, out);
}

// round 11
// speedup vs baseline: 1.1932x; 1.0633x over previous
#include <cuda_runtime.h>
#include <cuda_bf16.h>
#include <cstdint>

// RBF_Conv2d: x (16,1,256,256) f32, w (64,1,5,5) f32 -> out (16,64,252,252) f32
// out[b,o,h,w] = exp(-0.5 * d^2 / var_hw),  d = sqrt(max(||patch-w||^2,1e-12))
// var_hw = sample var (ddof=1) of d over the (B*O)=1024 matrix at pixel (h,w)
// Persistent h-strip blocks with rolling 6-slot row buffer + register prefetch.
// Warp reductions via fixed-point redux.sync.add.u32; Chan two-level variance merge.

#define B_  16
#define O_  64
#define HO  252
#define WO  252
#define WT  12      // w-pixels per block (252 = 21*12)
#define WIN 16      // window cols staged
#define NQ  6       // WT/2 packed pairs
#define STRIP 18    // h-rows per block (252 = 14*18)

#define SCALE2  1.099511627776e12f     // 2^40  (applied to d^2)
#define INV_S2  9.094947017729282e-13f // 2^-40
#define S2_RES  5.9604644775390625e-8f // 2^-24 (pass-2 rescale -> 2^16 fixed point)
#define S2_BACK 1.52587890625e-5f      // 2^-16

typedef unsigned long long u64;

__device__ __forceinline__ u64 fma2(u64 a, u64 b, u64 c) {
    u64 d; asm("fma.rn.f32x2 %0, %1, %2, %3;" : "=l"(d) : "l"(a), "l"(b), "l"(c)); return d;
}
__device__ __forceinline__ u64 add2(u64 a, u64 b) {
    u64 d; asm("add.rn.f32x2 %0, %1, %2;" : "=l"(d) : "l"(a), "l"(b)); return d;
}
__device__ __forceinline__ u64 pack2(float lo, float hi) {
    u64 d; asm("mov.b64 %0, {%1, %2};" : "=l"(d) : "f"(lo), "f"(hi)); return d;
}
__device__ __forceinline__ void unpack2(u64 v, float& lo, float& hi) {
    asm("mov.b64 {%0, %1}, %2;" : "=f"(lo), "=f"(hi) : "l"(v));
}
// odd-aligned pair {hi(a), lo(b)} built in registers (ALU pipe, no LDS)
__device__ __forceinline__ u64 mkodd(u64 a, u64 b) {
    u64 r;
    asm("{\n\t"
        ".reg .b32 alo, ahi, blo, bhi;\n\t"
        "mov.b64 {alo, ahi}, %1;\n\t"
        "mov.b64 {blo, bhi}, %2;\n\t"
        "mov.b64 %0, {ahi, blo};\n\t"
        "}" : "=l"(r) : "l"(a), "l"(b));
    return r;
}
__device__ __forceinline__ unsigned redux_u32(unsigned v) {
    unsigned r; asm("redux.sync.add.u32 %0, %1, 0xffffffff;" : "=r"(r) : "r"(v)); return r;
}
__device__ __forceinline__ float ex2_approx(float a) {
    float r; asm("ex2.approx.ftz.f32 %0, %1;" : "=f"(r) : "f"(a)); return r;
}
__device__ __forceinline__ float sqrt_approx(float a) {
    float r; asm("sqrt.approx.ftz.f32 %0, %1;" : "=f"(r) : "f"(a)); return r;
}

__global__ __launch_bounds__(512, 2)
void rbf_conv2d_kernel(const float* __restrict__ x,
                       const float* __restrict__ w,
                       float* __restrict__ out)
{
    __shared__ __align__(16) float xs [B_][6][WIN];  // rolling row buffer (6 slots)
    __shared__ __align__(16) float ws [25][O_];      // weights transposed [k][o]
    __shared__ __align__(16) float wns[O_];          // wn[o]*2^40
    __shared__ __align__(16) float pns[B_][WT];      // patch norms *2^40
    __shared__ __align__(16) float redC[WT][16];     // [w][warp] warp sums of d (2^20)
    __shared__ __align__(16) float redS[WT][16];     // [w][warp] warp S2 (2^16)
    __shared__ __align__(16) float cinv_s[WT];

    const int tid  = threadIdx.x;
    const int h0   = blockIdx.y * STRIP;
    const int w0   = blockIdx.x * WT;
    const int lane = tid & 31;
    const int warp = tid >> 5;           // == batch index b (warp-uniform)
    const int b    = warp;
    const int o0   = lane * 2;

    // ---- one-time staging: weights transposed + first 4 window rows ----
    for (int i = tid; i < 25 * O_; i += 512) {
        int k = i >> 6, o = i & 63;
        ws[k][o] = w[o * 25 + k];
    }
    for (int i = tid; i < B_ * 4 * WIN; i += 512) {
        int bb = i >> 6;
        int r  = (i >> 4) & 3;
        int c  = i & 15;
        xs[bb][r][c] = x[bb * 65536 + (h0 + r) * 256 + (w0 + c)];
    }
    // prefetch row h0+4 into registers
    float v = 0.f;
    const int pb = tid >> 4, pc = tid & 15;   // prefetch coords (tid<256)
    if (tid < 256)
        v = x[pb * 65536 + (h0 + 4) * 256 + (w0 + pc)];
    __syncthreads();

    // ---- weight norms (scaled 2^40), once ----
    if (tid < O_) {
        float s = 0.f;
        #pragma unroll
        for (int k = 0; k < 25; k++) {
            float t = ws[k][tid];
            s = fmaf(t, t, s);
        }
        wns[tid] = s * SCALE2;
    }
    // (visibility of wns/v-STS covered by the per-iteration barrier below)

    const u64 m2 = pack2(-2.f * SCALE2, -2.f * SCALE2);

    for (int it = 0; it < STRIP; it++) {
        const int h = h0 + it;
        // slot indices for window rows h..h+4
        int sr[5];
        sr[0] = it % 6;
        #pragma unroll
        for (int r = 1; r < 5; r++) { sr[r] = sr[r - 1] + 1; if (sr[r] == 6) sr[r] = 0; }

        // ---- store prefetched row (h+4) into its slot ----
        if (tid < 256) xs[pb][sr[4]][pc] = v;
        __syncthreads();

        // ---- patch norms (192 threads), scaled 2^40 ----
        if (tid < B_ * WT) {
            int bb = tid / WT, wi = tid % WT;
            float s = 0.f;
            #pragma unroll
            for (int kh = 0; kh < 5; kh++) {
                const float* row = &xs[bb][sr[kh]][0];
                #pragma unroll
                for (int kw = 0; kw < 5; kw++) {
                    float t = row[wi + kw];
                    s = fmaf(t, t, s);
                }
            }
            pns[bb][wi] = s * SCALE2;
        }
        // ---- prefetch next row (h+5) — latency hidden behind mainloop ----
        if (tid < 256) {
            int row = h + 5; if (row > 255) row = 255;   // clamp; last value unused
            v = x[pb * 65536 + row * 256 + (w0 + pc)];
        }
        __syncthreads();

        // ---- mainloop: tile 1b x 2o x 12w (6 packed pairs) ----
        u64 acc0[NQ], acc1[NQ];
        #pragma unroll
        for (int q = 0; q < NQ; q++) { acc0[q] = 0ull; acc1[q] = 0ull; }

        #pragma unroll
        for (int kh = 0; kh < 5; kh++) {
            u64 ev[8];
            {
                const uint4* p = (const uint4*)&xs[b][sr[kh]][0];
                #pragma unroll
                for (int t = 0; t < 4; t++) {
                    uint4 q4 = p[t];
                    ev[2 * t]     = (u64)q4.x | ((u64)q4.y << 32);
                    ev[2 * t + 1] = (u64)q4.z | ((u64)q4.w << 32);
                }
            }
            u64 od[7];
            #pragma unroll
            for (int i = 0; i < 7; i++) od[i] = mkodd(ev[i], ev[i + 1]);

            #pragma unroll
            for (int kw = 0; kw < 5; kw++) {
                float2 wv = *(const float2*)&ws[kh * 5 + kw][o0];
                u64 wp0 = pack2(wv.x, wv.x);
                u64 wp1 = pack2(wv.y, wv.y);
                #pragma unroll
                for (int q = 0; q < NQ; q++) {
                    u64 m = ((kw & 1) == 0) ? ev[q + (kw >> 1)] : od[q + ((kw - 1) >> 1)];
                    acc0[q] = fma2(m, wp0, acc0[q]);
                    acc1[q] = fma2(m, wp1, acc1[q]);
                }
            }
        }

        // ---- d_s = sqrt(max(d2*2^40, 1.1)) = d*2^20; local per-w sums ----
        float2 wnv = *(const float2*)&wns[o0];
        float dist[2][WT];
        float sums[WT];
        #pragma unroll
        for (int wi = 0; wi < WT; wi++) sums[wi] = 0.f;

        const u64* pnp = (const u64*)&pns[b][0];
        #pragma unroll
        for (int j = 0; j < 2; j++) {
            const float wn = j ? wnv.y : wnv.x;
            const u64 wnp = pack2(wn, wn);
            #pragma unroll
            for (int q = 0; q < NQ; q++) {
                u64 d2p = fma2(j ? acc1[q] : acc0[q], m2, add2(pnp[q], wnp));
                float a, bb;
                unpack2(d2p, a, bb);
                a  = fmaxf(a,  1.0995f);     // 1e-12 * 2^40
                bb = fmaxf(bb, 1.0995f);
                float da = sqrt_approx(a);
                float db = sqrt_approx(bb);
                dist[j][2 * q]     = da;
                dist[j][2 * q + 1] = db;
                sums[2 * q]     += da;
                sums[2 * q + 1] += db;
            }
        }

        // ---- warp sum of d over 64 o's via u32 redux ----
        float csumf[WT];
        #pragma unroll
        for (int wi = 0; wi < WT; wi++) {
            unsigned su = __float2uint_rn(sums[wi]);
            csumf[wi] = __uint2float_rn(redux_u32(su));
        }
        if (lane == 0) {
            #pragma unroll
            for (int wi = 0; wi < WT; wi++) redC[wi][warp] = csumf[wi];
        }

        // ---- warp-local S2 = Σ(d - c_w)^2 (2^40 -> 2^16 fixed point) ----
        #pragma unroll
        for (int wi = 0; wi < WT; wi++) {
            float dd0 = fmaf(csumf[wi], -1.0f / 64.0f, dist[0][wi]);
            float dd1 = fmaf(csumf[wi], -1.0f / 64.0f, dist[1][wi]);
            float s2 = fmaf(dd1, dd1, dd0 * dd0);
            unsigned su = __float2uint_rn(s2 * S2_RES);
            unsigned r = redux_u32(su);
            if (lane == 0) redS[wi][warp] = __uint2float_rn(r);
        }
        __syncthreads();

        // ---- finalize (12 threads): Chan merge of 16 warp stats ----
        if (tid < WT) {
            const float4* cp = (const float4*)&redC[tid][0];
            float4 c0 = cp[0], c1 = cp[1], c2 = cp[2], c3 = cp[3];
            const float4* sp = (const float4*)&redS[tid][0];
            float4 s0 = sp[0], s1 = sp[1], s2v = sp[2], s3 = sp[3];
            float csum = ((c0.x + c0.y) + (c0.z + c0.w)) + ((c1.x + c1.y) + (c1.z + c1.w))
                       + ((c2.x + c2.y) + (c2.z + c2.w)) + ((c3.x + c3.y) + (c3.z + c3.w));
            float S2w  = ((s0.x + s0.y) + (s0.z + s0.w)) + ((s1.x + s1.y) + (s1.z + s1.w))
                       + ((s2v.x + s2v.y) + (s2v.z + s2v.w)) + ((s3.x + s3.y) + (s3.z + s3.w));
            float mean = csum * (1.0f / 1024.0f);
            float bsum = 0.f;
            float cw[16] = {c0.x, c0.y, c0.z, c0.w, c1.x, c1.y, c1.z, c1.w,
                            c2.x, c2.y, c2.z, c2.w, c3.x, c3.y, c3.z, c3.w};
            #pragma unroll
            for (int r = 0; r < 16; r++) {
                float dd = fmaf(cw[r], 1.0f / 64.0f, -mean);
                bsum = fmaf(dd, dd, bsum);
            }
            float S2tot = fmaf(S2w, S2_BACK, 64.0f * bsum * INV_S2);
            float var = S2tot * (1.0f / 1023.0f);
            // out = exp2( d^2 * (-0.5*log2(e)/var) ); d_s^2 = d^2 * 2^40
            cinv_s[tid] = (-0.72134752044448170368f * INV_S2) / var;
        }
        __syncthreads();

        float cl[WT];
        #pragma unroll
        for (int wi = 0; wi < WT; wi++) cl[wi] = cinv_s[wi];

        // ---- write out: per (b,o) 12 contiguous floats (float4 x3) ----
        #pragma unroll
        for (int j = 0; j < 2; j++) {
            size_t base = ((size_t)(b * O_ + (o0 + j)) * HO + h) * WO + w0;
            #pragma unroll
            for (int g = 0; g < WT; g += 4) {
                float d0 = dist[j][g + 0];
                float d1 = dist[j][g + 1];
                float d2v = dist[j][g + 2];
                float d3 = dist[j][g + 3];
                float4 vv;
                vv.x = ex2_approx(cl[g + 0] * d0 * d0);
                vv.y = ex2_approx(cl[g + 1] * d1 * d1);
                vv.z = ex2_approx(cl[g + 2] * d2v * d2v);
                vv.w = ex2_approx(cl[g + 3] * d3 * d3);
                *(float4*)&out[base + g] = vv;
            }
        }
    }
}

extern "C" void kernel_launch(void* const* d_in, const int* in_sizes, int n_in,
                              void* d_out, int out_size)
{
    const float* x = (const float*)d_in[0];      // (16,1,256,256)
    const float* w = (const float*)d_in[1];      // (64,1,5,5)
    float* out = (float*)d_out;                  // (16,64,252,252)

    dim3 grid(WO / WT, HO / STRIP);              // (21, 14) = 294 blocks, one wave
    rbf_conv2d_kernel<<<grid, 512>>>(x, w, out);
}